// round 15
// baseline (speedup 1.0000x reference)
#include <cuda_runtime.h>
#include <cuda_bf16.h>
#include <mma.h>
#include <math.h>

using namespace nvcuda;

#define B_    4
#define T_    16
#define HW    64
#define PLANE 4096

typedef __nv_bfloat16 bf16;

// activations, chunk-planar: [buf][ (b*T+t)*4+kc ][px][16ch], hi & lo planes.
// buf0 = x (kc 0..1), buf1 = L0 out, buf2 = L1 out, buf3 = L2 out.
__device__ bf16 g_Ah[4][(size_t)B_ * T_ * 4 * PLANE * 16];
__device__ bf16 g_Al[4][(size_t)B_ * T_ * 4 * PLANE * 16];
// weights reordered: [((l*9+tap)*128+ci)*256 + co'], co' = half*128 + m*4 + gate
__device__ bf16 g_Bh[3 * 9 * 128 * 256];
__device__ bf16 g_Bl[3 * 9 * 128 * 256];
// cell state, channels-last per layer
__device__ float g_cst[3][(size_t)B_ * PLANE * 64];

__device__ __forceinline__ float tanh_fast(float x) {
    float y; asm("tanh.approx.f32 %0,%1;" : "=f"(y) : "f"(x)); return y;
}
__device__ __forceinline__ float sigm(float v) { return fmaf(tanh_fast(0.5f * v), 0.5f, 0.5f); }
__device__ __forceinline__ size_t aidx(int b, int t, int kc, int px) {
    return ((((size_t)(b * T_ + t)) * 4 + kc) * PLANE + px) * 16;
}
__device__ __forceinline__ void cp16(void* d, const void* s) {
    unsigned sd = (unsigned)__cvta_generic_to_shared(d);
    asm volatile("cp.async.cg.shared.global [%0],[%1],16;" :: "r"(sd), "l"(s) : "memory");
}

__global__ void prep_x(const float* __restrict__ x) {
    size_t i = (size_t)blockIdx.x * 256 + threadIdx.x;
    if (i >= (size_t)B_ * T_ * 32 * PLANE) return;
    int px = (int)(i & 4095);
    size_t r = i >> 12;
    int ci = (int)(r & 31);
    size_t bt = r >> 5;
    float v = x[i];
    bf16 h = __float2bfloat16(v);
    bf16 l = __float2bfloat16(v - __bfloat162float(h));
    size_t o = ((bt * 4 + (ci >> 4)) * PLANE + px) * 16 + (ci & 15);
    g_Ah[0][o] = h; g_Al[0][o] = l;
}

__global__ void prep_w(const float* __restrict__ g0, const float* __restrict__ g1,
                       const float* __restrict__ g2) {
    int i = blockIdx.x * 256 + threadIdx.x;
    if (i >= 3 * 9 * 128 * 256) return;
    int n   = i & 255;
    int ci  = (i >> 8) & 127;
    int lt  = i >> 15;          // l*9+tap
    int tap = lt % 9, l = lt / 9;
    int CC  = (l == 0) ? 96 : 128;
    bf16 h = __float2bfloat16(0.f), lo = h;
    if (ci < CC) {
        int half = n >> 7, n7 = n & 127, g = n7 & 3, m = n7 >> 2;
        int co = g * 64 + half * 32 + m;
        const float* gw = (l == 0) ? g0 : ((l == 1) ? g1 : g2);
        float v = gw[(size_t)(co * CC + ci) * 9 + tap];
        h  = __float2bfloat16(v);
        lo = __float2bfloat16(v - __bfloat162float(h));
    }
    g_Bh[i] = h; g_Bl[i] = lo;
}

// CTA: 1 image row (64 px) x 128 gate-cols (co' = m*4+gate, 32 channels).
// 4 warps: warp w = px cols [16w,16w+16). Accum: 8 frags (16px x 128 co').
template <int LAYER, int CINX, int DIL>
__global__ void __launch_bounds__(128) step_mma(
    const float* __restrict__ gb, const float* __restrict__ rw,
    const float* __restrict__ rb, float* __restrict__ out, int t)
{
    constexpr int CC  = CINX + 64;
    constexpr int KCX = CINX / 16, KCT = CC / 16;
    constexpr int HS  = (1 + 2 * DIL) * 1152;   // halo elems/plane (72*16 per row)

    extern __shared__ char smraw[];
    bf16*  hh = (bf16*)smraw;          // halo hi
    bf16*  hl = hh + HS;               // halo lo
    float* ds = (float*)smraw;         // epilogue D (64px x 128), reuses stage
    float* xs = ds + 8192;             // layer0 residual x stage (64px x 32ci)

    const int tid  = threadIdx.x;
    const int w    = tid >> 5;
    const int row  = blockIdx.x, half = blockIdx.y, b = blockIdx.z;

    // zero stage once: borders & OOB rows persist as zero across kc iterations
    for (int i = tid; i < 2 * HS / 8; i += 128)
        ((float4*)hh)[i] = make_float4(0.f, 0.f, 0.f, 0.f);
    __syncthreads();

    wmma::fragment<wmma::accumulator, 16, 16, 16, float> acc[8];
#pragma unroll
    for (int j = 0; j < 8; j++) wmma::fill_fragment(acc[j], 0.f);

    const int  kct = (t > 0) ? KCT : KCX;
    const bf16 *inH = g_Ah[LAYER], *inL = g_Al[LAYER];
    const bf16 *ouH = g_Ah[LAYER + 1], *ouL = g_Al[LAYER + 1];

    for (int kc = 0; kc < kct; kc++) {
        // stage: one cp16 per thread per (row, plane); 64 cols x 16ch = 1024 el
#pragma unroll 1
        for (int hr = 0; hr < 1 + 2 * DIL; hr++) {
            int r = row - DIL + hr;
            if (r < 0 || r >= HW) continue;
            const bf16* sH = (kc < KCX) ? inH : ouH;
            const bf16* sL = (kc < KCX) ? inL : ouL;
            size_t sh = (kc < KCX) ? aidx(b, t, kc, r * 64)
                                   : aidx(b, t - 1, kc - KCX, r * 64);
            cp16(hh + hr * 1152 + DIL * 16 + tid * 8, sH + sh + tid * 8);
            cp16(hl + hr * 1152 + DIL * 16 + tid * 8, sL + sh + tid * 8);
        }
        asm volatile("cp.async.commit_group;\n\tcp.async.wait_group 0;" ::: "memory");
        __syncthreads();

#pragma unroll 1
        for (int tap = 0; tap < 9; tap++) {
            const int dy = tap / 3, dx = tap % 3;
            const int aoff = (dy * DIL) * 1152 + (w * 16 + dx * DIL) * 16;
            wmma::fragment<wmma::matrix_a, 16, 16, 16, bf16, wmma::row_major> aH, aL;
            wmma::load_matrix_sync(aH, hh + aoff, 16);
            wmma::load_matrix_sync(aL, hl + aoff, 16);
            const size_t wb = (((size_t)(LAYER * 9 + tap) * 128) + kc * 16) * 256 + half * 128;
#pragma unroll
            for (int cof = 0; cof < 8; cof++) {
                wmma::fragment<wmma::matrix_b, 16, 16, 16, bf16, wmma::row_major> bH, bL;
                wmma::load_matrix_sync(bH, g_Bh + wb + cof * 16, 256);
                wmma::load_matrix_sync(bL, g_Bl + wb + cof * 16, 256);
                wmma::mma_sync(acc[cof], aH, bH, acc[cof]);
                wmma::mma_sync(acc[cof], aL, bH, acc[cof]);
                wmma::mma_sync(acc[cof], aH, bL, acc[cof]);
            }
        }
        __syncthreads();   // done reading halo before next kc overwrites
    }

    // ---- epilogue ----
#pragma unroll
    for (int cof = 0; cof < 8; cof++)
        wmma::store_matrix_sync(ds + (w * 16) * 128 + cof * 16, acc[cof], 128,
                                wmma::mem_row_major);
    __syncthreads();

    if (LAYER == 0) {
        for (int i = tid; i < 64 * 32; i += 128) {
            int pxc = i >> 5, ci = i & 31;
            size_t o = aidx(b, t, ci >> 4, row * 64 + pxc) + (ci & 15);
            xs[i] = __bfloat162float(inH[o]) + __bfloat162float(inL[o]);
        }
        __syncthreads();
    }

    for (int i = tid; i < 64 * 32; i += 128) {
        int pxc = i & 63, m = i >> 6;
        int ch  = half * 32 + m;
        int pxg = row * 64 + pxc;
        float4 g4 = *(float4*)&ds[pxc * 128 + m * 4];   // (i,f,g,o) for ch

        float res;
        if (LAYER == 0) {
            res = __ldg(rb + ch);
#pragma unroll
            for (int ci = 0; ci < 32; ci++)
                res = fmaf(__ldg(rw + ch * 32 + ci), xs[pxc * 32 + ci], res);
        } else {
            size_t o = aidx(b, t, ch >> 4, pxg) + (ch & 15);
            res = __bfloat162float(inH[o]) + __bfloat162float(inL[o]);
        }

        float iv = sigm(g4.x + __ldg(gb + ch));
        float fv = sigm(g4.y + __ldg(gb + 64 + ch));
        float gv = tanh_fast(g4.z + __ldg(gb + 128 + ch));
        float ov = sigm(g4.w + __ldg(gb + 192 + ch));

        float* cp = &g_cst[LAYER][((size_t)b * PLANE + pxg) * 64 + ch];
        float cold = (t > 0) ? *cp : 0.f;
        float cn = fv * cold + iv * gv;
        *cp = cn;
        float h = ov * tanh_fast(cn) + res;

        bf16 hb = __float2bfloat16(h);
        bf16 lb = __float2bfloat16(h - __bfloat162float(hb));
        size_t oo = aidx(b, t, ch >> 4, pxg) + (ch & 15);
        g_Ah[LAYER + 1][oo] = hb;
        g_Al[LAYER + 1][oo] = lb;
        if (LAYER == 2)
            out[(((size_t)(b * T_ + t)) * 64 + ch) * PLANE + pxg] = h;
    }
}

static constexpr int SMB(int dil, int layer) {
    int stage = 2 * (1 + 2 * dil) * 1152 * 2;
    int epi   = 32768 + (layer == 0 ? 8192 : 0);
    return stage > epi ? stage : epi;
}

extern "C" void kernel_launch(void* const* d_in, const int* in_sizes, int n_in,
                              void* d_out, int out_size)
{
    (void)in_sizes; (void)n_in; (void)out_size;
    const float* x   = (const float*)d_in[0];
    const float* gw0 = (const float*)d_in[1];
    const float* gb0 = (const float*)d_in[2];
    const float* gw1 = (const float*)d_in[3];
    const float* gb1 = (const float*)d_in[4];
    const float* gw2 = (const float*)d_in[5];
    const float* gb2 = (const float*)d_in[6];
    const float* rw0 = (const float*)d_in[7];
    const float* rb0 = (const float*)d_in[8];
    float* out = (float*)d_out;

    constexpr int SM0 = SMB(1, 0), SM1 = SMB(2, 1), SM2 = SMB(4, 2);

    static cudaStream_t s1 = nullptr, s2 = nullptr;
    static cudaEvent_t e0[T_], e1[T_], f1, f2;
    if (s1 == nullptr) {
        cudaFuncSetAttribute(step_mma<0, 32, 1>, cudaFuncAttributeMaxDynamicSharedMemorySize, SM0);
        cudaFuncSetAttribute(step_mma<1, 64, 2>, cudaFuncAttributeMaxDynamicSharedMemorySize, SM1);
        cudaFuncSetAttribute(step_mma<2, 64, 4>, cudaFuncAttributeMaxDynamicSharedMemorySize, SM2);
        cudaStreamCreateWithFlags(&s1, cudaStreamNonBlocking);
        cudaStreamCreateWithFlags(&s2, cudaStreamNonBlocking);
        for (int t = 0; t < T_; t++) {
            cudaEventCreateWithFlags(&e0[t], cudaEventDisableTiming);
            cudaEventCreateWithFlags(&e1[t], cudaEventDisableTiming);
        }
        cudaEventCreateWithFlags(&f1, cudaEventDisableTiming);
        cudaEventCreateWithFlags(&f2, cudaEventDisableTiming);
    }

    prep_x<<<(int)(((size_t)B_ * T_ * 32 * PLANE + 255) / 256), 256>>>(x);
    prep_w<<<(3 * 9 * 128 * 256 + 255) / 256, 256>>>(gw0, gw1, gw2);

    dim3 grid(64, 2, B_);
    for (int t = 0; t < T_; t++) {
        step_mma<0, 32, 1><<<grid, 128, SM0, 0>>>(gb0, rw0, rb0, out, t);
        cudaEventRecord(e0[t], 0);
        cudaStreamWaitEvent(s1, e0[t], 0);
        step_mma<1, 64, 2><<<grid, 128, SM1, s1>>>(gb1, nullptr, nullptr, out, t);
        cudaEventRecord(e1[t], s1);
        cudaStreamWaitEvent(s2, e1[t], 0);
        step_mma<2, 64, 4><<<grid, 128, SM2, s2>>>(gb2, nullptr, nullptr, out, t);
    }
    cudaEventRecord(f1, s1);
    cudaEventRecord(f2, s2);
    cudaStreamWaitEvent(0, f1, 0);
    cudaStreamWaitEvent(0, f2, 0);
}

// round 16
// speedup vs baseline: 2.2498x; 2.2498x over previous
#include <cuda_runtime.h>
#include <cuda_bf16.h>
#include <mma.h>
#include <math.h>

using namespace nvcuda;

#define B_    4
#define T_    16
#define HW    64
#define PLANE 4096

typedef __nv_bfloat16 bf16;

// activations, chunk-planar: [buf][ (b*T+t)*4+kc ][px][16ch], hi & lo planes.
__device__ bf16 g_Ah[4][(size_t)B_ * T_ * 4 * PLANE * 16];
__device__ bf16 g_Al[4][(size_t)B_ * T_ * 4 * PLANE * 16];
// weights tiled: [((((l*9+tap)*8+kc)*2+half)*8+cof)*256 + ci16*16 + n16]
__device__ bf16 g_Bh[3 * 9 * 8 * 2 * 2048];
__device__ bf16 g_Bl[3 * 9 * 8 * 2 * 2048];
__device__ float g_cst[3][(size_t)B_ * PLANE * 64];

__device__ __forceinline__ float tanh_fast(float x) {
    float y; asm("tanh.approx.f32 %0,%1;" : "=f"(y) : "f"(x)); return y;
}
__device__ __forceinline__ float sigm(float v) { return fmaf(tanh_fast(0.5f * v), 0.5f, 0.5f); }
__device__ __forceinline__ size_t aidx(int b, int t, int kc, int px) {
    return ((((size_t)(b * T_ + t)) * 4 + kc) * PLANE + px) * 16;
}
__device__ __forceinline__ void cp16(void* d, const void* s) {
    unsigned sd = (unsigned)__cvta_generic_to_shared(d);
    asm volatile("cp.async.cg.shared.global [%0],[%1],16;" :: "r"(sd), "l"(s) : "memory");
}
__device__ __forceinline__ void cpc() { asm volatile("cp.async.commit_group;" ::: "memory"); }
__device__ __forceinline__ void cpw0() { asm volatile("cp.async.wait_group 0;" ::: "memory"); }

__global__ void prep_x(const float* __restrict__ x) {
    size_t i = (size_t)blockIdx.x * 256 + threadIdx.x;
    if (i >= (size_t)B_ * T_ * 32 * PLANE) return;
    int px = (int)(i & 4095);
    size_t r = i >> 12;
    int ci = (int)(r & 31);
    size_t bt = r >> 5;
    float v = x[i];
    bf16 h = __float2bfloat16(v);
    bf16 l = __float2bfloat16(v - __bfloat162float(h));
    size_t o = ((bt * 4 + (ci >> 4)) * PLANE + px) * 16 + (ci & 15);
    g_Ah[0][o] = h; g_Al[0][o] = l;
}

__global__ void prep_w(const float* __restrict__ g0, const float* __restrict__ g1,
                       const float* __restrict__ g2) {
    int i = blockIdx.x * 256 + threadIdx.x;
    if (i >= 3 * 9 * 8 * 2 * 2048) return;
    int n16  = i & 15;
    int ci16 = (i >> 4) & 15;
    int cof  = (i >> 8) & 7;
    int half = (i >> 11) & 1;
    int kc   = (i >> 12) & 7;
    int lt   = i >> 15;               // l*9 + tap
    int tap = lt % 9, l = lt / 9;
    int CC  = (l == 0) ? 96 : 128;
    int ci  = kc * 16 + ci16;
    int n   = cof * 16 + n16;         // local co' in half: m*4+gate
    bf16 h = __float2bfloat16(0.f), lo = h;
    if (ci < CC) {
        int g = n & 3, m = n >> 2;
        int co = g * 64 + half * 32 + m;
        const float* gw = (l == 0) ? g0 : ((l == 1) ? g1 : g2);
        float v = gw[(size_t)(co * CC + ci) * 9 + tap];
        h  = __float2bfloat16(v);
        lo = __float2bfloat16(v - __bfloat162float(h));
    }
    g_Bh[i] = h; g_Bl[i] = lo;
}

// CTA: 1 image row (64 px) x 128 gate-cols; 4 warps, warp w = px [16w,16w+16).
template <int LAYER, int CINX, int DIL>
__global__ void __launch_bounds__(128) step_mma(
    const float* __restrict__ gb, const float* __restrict__ rw,
    const float* __restrict__ rb, float* __restrict__ out, int t)
{
    constexpr int KCX = CINX / 16, KCT = (CINX + 64) / 16;
    constexpr int HS  = (1 + 2 * DIL) * 1152;   // halo elems/plane

    extern __shared__ char smraw[];
    bf16*  hh  = (bf16*)smraw;          // halo hi
    bf16*  hl  = hh + HS;               // halo lo
    bf16*  bsm = hl + HS;               // B hi: 2 bufs x 2048
    bf16*  bll = bsm + 4096;            // B lo: 2 bufs x 2048
    float* ds  = (float*)smraw;         // epilogue D (64px x 128), reuses stage
    float* xs  = ds + 8192;             // layer0 residual x stage

    const int tid  = threadIdx.x;
    const int w    = tid >> 5;
    const int row  = blockIdx.x, half = blockIdx.y, b = blockIdx.z;

    for (int i = tid; i < 2 * HS / 8; i += 128)
        ((float4*)hh)[i] = make_float4(0.f, 0.f, 0.f, 0.f);
    __syncthreads();

    wmma::fragment<wmma::accumulator, 16, 16, 16, float> acc[8];
#pragma unroll
    for (int j = 0; j < 8; j++) wmma::fill_fragment(acc[j], 0.f);

    const int  kct = (t > 0) ? KCT : KCX;
    const bf16 *inH = g_Ah[LAYER], *inL = g_Al[LAYER];
    const bf16 *ouH = g_Ah[LAYER + 1], *ouL = g_Al[LAYER + 1];

    auto stageB = [&](int kc, int tap, int bi) {
        size_t gbo = (((size_t)(LAYER * 9 + tap) * 8 + kc) * 2 + half) * 2048;
        cp16(bsm + bi * 2048 + tid * 16,     g_Bh + gbo + tid * 16);
        cp16(bsm + bi * 2048 + tid * 16 + 8, g_Bh + gbo + tid * 16 + 8);
        cp16(bll + bi * 2048 + tid * 16,     g_Bl + gbo + tid * 16);
        cp16(bll + bi * 2048 + tid * 16 + 8, g_Bl + gbo + tid * 16 + 8);
    };

    for (int kc = 0; kc < kct; kc++) {
#pragma unroll 1
        for (int hr = 0; hr < 1 + 2 * DIL; hr++) {
            int r = row - DIL + hr;
            if (r < 0 || r >= HW) continue;
            const bf16* sH = (kc < KCX) ? inH : ouH;
            const bf16* sL = (kc < KCX) ? inL : ouL;
            size_t sh = (kc < KCX) ? aidx(b, t, kc, r * 64)
                                   : aidx(b, t - 1, kc - KCX, r * 64);
            cp16(hh + hr * 1152 + DIL * 16 + tid * 8, sH + sh + tid * 8);
            cp16(hl + hr * 1152 + DIL * 16 + tid * 8, sL + sh + tid * 8);
        }
        stageB(kc, 0, 0);
        cpc(); cpw0();
        __syncthreads();

#pragma unroll 1
        for (int tap = 0; tap < 9; tap++) {
            if (tap < 8) { stageB(kc, tap + 1, (tap + 1) & 1); cpc(); }

            const int dy = tap / 3, dx = tap % 3;
            const int aoff = (dy * DIL) * 1152 + (w * 16 + dx * DIL) * 16;
            wmma::fragment<wmma::matrix_a, 16, 16, 16, bf16, wmma::row_major> aH, aL;
            wmma::load_matrix_sync(aH, hh + aoff, 16);
            wmma::load_matrix_sync(aL, hl + aoff, 16);
            const bf16* bh = bsm + (tap & 1) * 2048;
            const bf16* bl = bll + (tap & 1) * 2048;
#pragma unroll
            for (int cof = 0; cof < 8; cof++) {
                wmma::fragment<wmma::matrix_b, 16, 16, 16, bf16, wmma::row_major> bH, bL;
                wmma::load_matrix_sync(bH, bh + cof * 256, 16);
                wmma::load_matrix_sync(bL, bl + cof * 256, 16);
                wmma::mma_sync(acc[cof], aH, bH, acc[cof]);
                wmma::mma_sync(acc[cof], aL, bH, acc[cof]);
                wmma::mma_sync(acc[cof], aH, bL, acc[cof]);
            }
            if (tap < 8) cpw0();
            __syncthreads();
        }
    }

    // ---- epilogue ----
#pragma unroll
    for (int cof = 0; cof < 8; cof++)
        wmma::store_matrix_sync(ds + (w * 16) * 128 + cof * 16, acc[cof], 128,
                                wmma::mem_row_major);
    __syncthreads();

    if (LAYER == 0) {
        for (int i = tid; i < 64 * 32; i += 128) {
            int pxc = i >> 5, ci = i & 31;
            size_t o = aidx(b, t, ci >> 4, row * 64 + pxc) + (ci & 15);
            xs[i] = __bfloat162float(inH[o]) + __bfloat162float(inL[o]);
        }
        __syncthreads();
    }

    for (int i = tid; i < 64 * 32; i += 128) {
        int pxc = i & 63, m = i >> 6;
        int ch  = half * 32 + m;
        int pxg = row * 64 + pxc;
        float4 g4 = *(float4*)&ds[pxc * 128 + m * 4];   // (i,f,g,o)

        float res;
        if (LAYER == 0) {
            res = __ldg(rb + ch);
#pragma unroll
            for (int ci = 0; ci < 32; ci++)
                res = fmaf(__ldg(rw + ch * 32 + ci), xs[pxc * 32 + ci], res);
        } else {
            size_t o = aidx(b, t, ch >> 4, pxg) + (ch & 15);
            res = __bfloat162float(inH[o]) + __bfloat162float(inL[o]);
        }

        float iv = sigm(g4.x + __ldg(gb + ch));
        float fv = sigm(g4.y + __ldg(gb + 64 + ch));
        float gv = tanh_fast(g4.z + __ldg(gb + 128 + ch));
        float ov = sigm(g4.w + __ldg(gb + 192 + ch));

        float* cp = &g_cst[LAYER][((size_t)b * PLANE + pxg) * 64 + ch];
        float cold = (t > 0) ? *cp : 0.f;
        float cn = fv * cold + iv * gv;
        *cp = cn;
        float h = ov * tanh_fast(cn) + res;

        bf16 hb = __float2bfloat16(h);
        bf16 lb = __float2bfloat16(h - __bfloat162float(hb));
        size_t oo = aidx(b, t, ch >> 4, pxg) + (ch & 15);
        g_Ah[LAYER + 1][oo] = hb;
        g_Al[LAYER + 1][oo] = lb;
        if (LAYER == 2)
            out[(((size_t)(b * T_ + t)) * 64 + ch) * PLANE + pxg] = h;
    }
}

static constexpr int SMB(int dil, int layer) {
    int stage = 4 * (1 + 2 * dil) * 1152 + 16384;        // halo hi+lo + B bufs
    int epi   = 32768 + (layer == 0 ? 8192 : 0);
    return stage > epi ? stage : epi;
}

extern "C" void kernel_launch(void* const* d_in, const int* in_sizes, int n_in,
                              void* d_out, int out_size)
{
    (void)in_sizes; (void)n_in; (void)out_size;
    const float* x   = (const float*)d_in[0];
    const float* gw0 = (const float*)d_in[1];
    const float* gb0 = (const float*)d_in[2];
    const float* gw1 = (const float*)d_in[3];
    const float* gb1 = (const float*)d_in[4];
    const float* gw2 = (const float*)d_in[5];
    const float* gb2 = (const float*)d_in[6];
    const float* rw0 = (const float*)d_in[7];
    const float* rb0 = (const float*)d_in[8];
    float* out = (float*)d_out;

    constexpr int SM0 = SMB(1, 0), SM1 = SMB(2, 1), SM2 = SMB(4, 2);

    static cudaStream_t s1 = nullptr, s2 = nullptr;
    static cudaEvent_t e0[T_], e1[T_], f1, f2;
    if (s1 == nullptr) {
        cudaFuncSetAttribute(step_mma<0, 32, 1>, cudaFuncAttributeMaxDynamicSharedMemorySize, SM0);
        cudaFuncSetAttribute(step_mma<1, 64, 2>, cudaFuncAttributeMaxDynamicSharedMemorySize, SM1);
        cudaFuncSetAttribute(step_mma<2, 64, 4>, cudaFuncAttributeMaxDynamicSharedMemorySize, SM2);
        cudaStreamCreateWithFlags(&s1, cudaStreamNonBlocking);
        cudaStreamCreateWithFlags(&s2, cudaStreamNonBlocking);
        for (int t = 0; t < T_; t++) {
            cudaEventCreateWithFlags(&e0[t], cudaEventDisableTiming);
            cudaEventCreateWithFlags(&e1[t], cudaEventDisableTiming);
        }
        cudaEventCreateWithFlags(&f1, cudaEventDisableTiming);
        cudaEventCreateWithFlags(&f2, cudaEventDisableTiming);
    }

    prep_x<<<(int)(((size_t)B_ * T_ * 32 * PLANE + 255) / 256), 256>>>(x);
    prep_w<<<(3 * 9 * 8 * 2 * 2048 + 255) / 256, 256>>>(gw0, gw1, gw2);

    dim3 grid(64, 2, B_);
    for (int t = 0; t < T_; t++) {
        step_mma<0, 32, 1><<<grid, 128, SM0, 0>>>(gb0, rw0, rb0, out, t);
        cudaEventRecord(e0[t], 0);
        cudaStreamWaitEvent(s1, e0[t], 0);
        step_mma<1, 64, 2><<<grid, 128, SM1, s1>>>(gb1, nullptr, nullptr, out, t);
        cudaEventRecord(e1[t], s1);
        cudaStreamWaitEvent(s2, e1[t], 0);
        step_mma<2, 64, 4><<<grid, 128, SM2, s2>>>(gb2, nullptr, nullptr, out, t);
    }
    cudaEventRecord(f1, s1);
    cudaEventRecord(f2, s2);
    cudaStreamWaitEvent(0, f1, 0);
    cudaStreamWaitEvent(0, f2, 0);
}